// round 15
// baseline (speedup 1.0000x reference)
#include <cuda_runtime.h>
#include <cuda_bf16.h>
#include <cuda_fp16.h>
#include <math_constants.h>
#include <cstdint>

#define NMAX 50176
#define EMAX 800000
#define D    128
#define D2   256
#define MSG_EPS 1e-7f
#define SM_EPS  1e-16f
#define BN_EPS  1e-5f
#define LN_EPS  1e-5f
#define NPARTMAX 64
#define NBMAX 392
#define TILEB 34816          /* bytes per 128-row bf16 tile image (272B pitch) */

// ---------------- scratch (static device globals; no allocation) -------------
__device__ int   g_deg[NMAX];          // zero at entry (reset by scan_scatter)
__device__ int   g_offs[NMAX + 1];
__device__ int   g_cur[NMAX];
__device__ __align__(16) int g_srcs[EMAX];
__device__ int   g_partoffs[NPARTMAX];
__device__ int   g_done1;              // reset by K1 last block
__device__ int   g_done2;              // reset by K1 thread 0 (next replay)
__device__ float g_h1[(size_t)NMAX * D2];
__device__ float g_colsum[D2];         // zero at entry (reset by bnfinal)
__device__ float g_colsq[D2];
__device__ float g_bnscale[D2];
__device__ float g_bnshift[D2];
__device__ __align__(16) uint32_t g_ew[(size_t)NMAX * D];   // half2(E, W) per feature
__device__ __align__(16) unsigned char g_h0img_hi[(size_t)NBMAX * TILEB];
__device__ __align__(16) unsigned char g_h0img_lo[(size_t)NBMAX * TILEB];
__device__ __align__(16) unsigned char g_W1img_hi[69632];
__device__ __align__(16) unsigned char g_W1img_lo[69632];
__device__ __align__(16) unsigned char g_W2img_hi[69632];
__device__ __align__(16) unsigned char g_W2img_lo[69632];

// ---------------- helpers ----------------------------------------------------
__device__ __forceinline__ uint32_t smem_u32(const void* p) {
    uint32_t a;
    asm("{ .reg .u64 t; cvta.to.shared.u64 t, %1; cvt.u32.u64 %0, t; }" : "=r"(a) : "l"(p));
    return a;
}
__device__ __forceinline__ void ldsm_x4(uint32_t* r, uint32_t addr) {
    asm volatile("ldmatrix.sync.aligned.m8n8.x4.shared.b16 {%0,%1,%2,%3}, [%4];"
        : "=r"(r[0]), "=r"(r[1]), "=r"(r[2]), "=r"(r[3]) : "r"(addr));
}
__device__ __forceinline__ void mma16816(float* d, const uint32_t* a, const uint32_t* b) {
    asm volatile(
        "mma.sync.aligned.m16n8k16.row.col.f32.bf16.bf16.f32 "
        "{%0,%1,%2,%3}, {%4,%5,%6,%7}, {%8,%9}, {%0,%1,%2,%3};"
        : "+f"(d[0]), "+f"(d[1]), "+f"(d[2]), "+f"(d[3])
        : "r"(a[0]), "r"(a[1]), "r"(a[2]), "r"(a[3]), "r"(b[0]), "r"(b[1]));
}
__device__ __forceinline__ float ex2(float x) {
    float r;
    asm("ex2.approx.f32 %0, %1;" : "=f"(r) : "f"(x));
    return r;
}
#define CP_ASYNC16(dst_u32, src_ptr) \
    asm volatile("cp.async.cg.shared.global [%0], [%1], 16;" :: "r"(dst_u32), "l"(src_ptr))
#define CP_COMMIT() asm volatile("cp.async.commit_group;")
#define CP_WAIT0()  asm volatile("cp.async.wait_group 0;")

// fast bf16 hi/lo split: hi = truncate (PRMT), lo = fp32 residual (cvt.rn.bf16x2)
__device__ __forceinline__ void cvt8(const float* f, uint4& hv, uint4& lv) {
    unsigned h[4], l[4];
    #pragma unroll
    for (int j = 0; j < 4; j++) {
        uint32_t u0 = __float_as_uint(f[2*j]), u1 = __float_as_uint(f[2*j+1]);
        asm("prmt.b32 %0, %1, %2, 0x7632;" : "=r"(h[j]) : "r"(u0), "r"(u1));
        float l0 = f[2*j]   - __uint_as_float(u0 & 0xFFFF0000u);
        float l1 = f[2*j+1] - __uint_as_float(u1 & 0xFFFF0000u);
        asm("cvt.rn.bf16x2.f32 %0, %1, %2;" : "=r"(l[j]) : "f"(l1), "f"(l0));
    }
    hv = make_uint4(h[0], h[1], h[2], h[3]);
    lv = make_uint4(l[0], l[1], l[2], l[3]);
}
__device__ __forceinline__ uint32_t packEW(float xv, float c) {
    float v = fmaxf(xv, 0.f);
    float e = ex2(v * c);
    __half2 h = __floats2half2_rn(e, e * v);
    return *(uint32_t*)&h;
}

// ---------------- K1: weight images + EW table + histogram + chunk scan ------
__global__ void k1_init_hist(const float* __restrict__ W1, const float* __restrict__ W2,
                             const float* __restrict__ x, const float* __restrict__ t_ptr,
                             const int* __restrict__ dst, int e, int n, int npart) {
    int i = blockIdx.x * 1024 + threadIdx.x;
    if (i == 0) g_done2 = 0;
    if (i < 32768) {                          // W1^T: n<256, k<128
        int nn = i >> 7, k = i & 127;
        float w = W1[k * 256 + nn];
        __nv_bfloat16 hi = __float2bfloat16(w);
        __nv_bfloat16 lo = __float2bfloat16(w - __bfloat162float(hi));
        int off = nn * 272 + k * 2;
        *(unsigned short*)(g_W1img_hi + off) = __bfloat16_as_ushort(hi);
        *(unsigned short*)(g_W1img_lo + off) = __bfloat16_as_ushort(lo);
    } else if (i < 65536) {                   // W2^T: n<128, k<256
        int j = i - 32768;
        int nn = j >> 8, k = j & 255;
        float w = W2[k * 128 + nn];
        __nv_bfloat16 hi = __float2bfloat16(w);
        __nv_bfloat16 lo = __float2bfloat16(w - __bfloat162float(hi));
        int off = (k >> 7) * TILEB + nn * 272 + (k & 127) * 2;
        *(unsigned short*)(g_W2img_hi + off) = __bfloat16_as_ushort(hi);
        *(unsigned short*)(g_W2img_lo + off) = __bfloat16_as_ushort(lo);
    }
    if (i < n * 32) {
        float c = __ldg(t_ptr) * 1.4426950408889634f;
        int node = i >> 5, l = i & 31;
        float4 q = __ldg((const float4*)(x + (size_t)node * D) + l);
        uint4 u;
        u.x = packEW(q.x, c);
        u.y = packEW(q.y, c);
        u.z = packEW(q.z, c);
        u.w = packEW(q.w, c);
        *(uint4*)(g_ew + (size_t)node * D + l * 4) = u;
    }
    if (i < e) atomicAdd(&g_deg[dst[i]], 1);

    __threadfence();
    __shared__ int s_last;
    if (threadIdx.x == 0) s_last = (atomicAdd(&g_done1, 1) == (int)gridDim.x - 1);
    __syncthreads();
    if (!s_last) return;
    if (threadIdx.x == 0) g_done1 = 0;

    __shared__ int csum[NPARTMAX];
    __shared__ int sh[NPARTMAX];
    int t = threadIdx.x, lane = t & 31, w = t >> 5;
    for (int c2 = w; c2 < npart; c2 += 32) {
        int s = 0;
        for (int k = lane; k < 1024; k += 32) {
            int idx = (c2 << 10) + k;
            s += (idx < n) ? g_deg[idx] : 0;
        }
        #pragma unroll
        for (int o = 16; o > 0; o >>= 1) s += __shfl_xor_sync(0xffffffffu, s, o);
        if (lane == 0) csum[c2] = s;
    }
    __syncthreads();
    if (t < NPARTMAX) sh[t] = (t < npart) ? csum[t] : 0;
    __syncthreads();
    for (int o = 1; o < NPARTMAX; o <<= 1) {
        int add = (t < NPARTMAX && t >= o) ? sh[t - o] : 0;
        __syncthreads();
        if (t < NPARTMAX) sh[t] += add;
        __syncthreads();
    }
    if (t < npart) g_partoffs[t] = sh[t] - csum[t];
    if (t == npart - 1) g_offs[n] = sh[t];
}

// ---------------- fused local scan + grid barrier + scatter ------------------
__global__ void scan_scatter(const int* __restrict__ src, const int* __restrict__ dst,
                             int e, int n, int npart) {
    __shared__ int warpsums[32];
    int t = threadIdx.x, lane = t & 31, w = t >> 5;
    int i = blockIdx.x * 1024 + t;
    int v = (i < n) ? g_deg[i] : 0;
    int s = v;
    #pragma unroll
    for (int o = 1; o < 32; o <<= 1) {
        int u = __shfl_up_sync(0xffffffffu, s, o);
        if (lane >= o) s += u;
    }
    if (lane == 31) warpsums[w] = s;
    __syncthreads();
    if (w == 0) {
        int ws = warpsums[lane];
        #pragma unroll
        for (int o = 1; o < 32; o <<= 1) {
            int u = __shfl_up_sync(0xffffffffu, ws, o);
            if (lane >= o) ws += u;
        }
        warpsums[lane] = ws;
    }
    __syncthreads();
    if (i < n) {
        int ex = g_partoffs[blockIdx.x] + s - v + (w > 0 ? warpsums[w - 1] : 0);
        g_offs[i] = ex;
        g_cur[i] = ex;
        g_deg[i] = 0;
    }
    __syncthreads();
    __threadfence();
    if (t == 0) {
        atomicAdd(&g_done2, 1);
        while (atomicAdd(&g_done2, 0) < npart) { __nanosleep(64); }
    }
    __syncthreads();
    for (int j = blockIdx.x * 1024 + t; j < e; j += npart * 1024) {
        int pos = atomicAdd(&g_cur[dst[j]], 1);
        g_srcs[pos] = src[j];
    }
}

// ---------------- one-pass softmax aggregation via EW table ------------------
__device__ __forceinline__ void accEW(uint4 u, float& d0, float& n0, float& d1, float& n1,
                                      float& d2, float& n2, float& d3, float& n3) {
    float2 f;
    f = __half22float2(*(__half2*)&u.x); d0 += f.x; n0 += f.y;
    f = __half22float2(*(__half2*)&u.y); d1 += f.x; n1 += f.y;
    f = __half22float2(*(__half2*)&u.z); d2 += f.x; n2 += f.y;
    f = __half22float2(*(__half2*)&u.w); d3 += f.x; n3 += f.y;
}

__global__ void agg_kernel(const float* __restrict__ x, int n) {
    int gw   = (blockIdx.x * blockDim.x + threadIdx.x) >> 5;
    int lane = threadIdx.x & 31;
    if (gw >= n) return;
    int beg = g_offs[gw], end = g_offs[gw + 1];

    float n0 = 0.f, n1 = 0.f, n2 = 0.f, n3 = 0.f;
    float d0 = 0.f, d1 = 0.f, d2 = 0.f, d3 = 0.f;
    int e = beg;
    while (e < end && (e & 3)) {
        uint4 u = __ldg((const uint4*)(g_ew + (size_t)__ldg(&g_srcs[e]) * D) + lane);
        accEW(u, d0, n0, d1, n1, d2, n2, d3, n3);
        e++;
    }
    int e4 = e + ((end - e) & ~3);
    for (; e < e4; e += 4) {
        int4 s4 = __ldg((const int4*)(g_srcs + e));
        uint4 u0 = __ldg((const uint4*)(g_ew + (size_t)s4.x * D) + lane);
        uint4 u1 = __ldg((const uint4*)(g_ew + (size_t)s4.y * D) + lane);
        uint4 u2 = __ldg((const uint4*)(g_ew + (size_t)s4.z * D) + lane);
        uint4 u3 = __ldg((const uint4*)(g_ew + (size_t)s4.w * D) + lane);
        accEW(u0, d0, n0, d1, n1, d2, n2, d3, n3);
        accEW(u1, d0, n0, d1, n1, d2, n2, d3, n3);
        accEW(u2, d0, n0, d1, n1, d2, n2, d3, n3);
        accEW(u3, d0, n0, d1, n1, d2, n2, d3, n3);
    }
    for (; e < end; e++) {
        uint4 u = __ldg((const uint4*)(g_ew + (size_t)__ldg(&g_srcs[e]) * D) + lane);
        accEW(u, d0, n0, d1, n1, d2, n2, d3, n3);
    }
    float4 xq = __ldg((const float4*)(x + (size_t)gw * D) + lane);
    float hx = (n0 + MSG_EPS * d0) / (d0 + SM_EPS) + xq.x;
    float hy = (n1 + MSG_EPS * d1) / (d1 + SM_EPS) + xq.y;
    float hz = (n2 + MSG_EPS * d2) / (d2 + SM_EPS) + xq.z;
    float hw = (n3 + MSG_EPS * d3) / (d3 + SM_EPS) + xq.w;

    uint32_t ux = __float_as_uint(hx), uy = __float_as_uint(hy);
    uint32_t uz = __float_as_uint(hz), uw = __float_as_uint(hw);
    uint32_t hi0, hi1, lo0, lo1;
    asm("prmt.b32 %0, %1, %2, 0x7632;" : "=r"(hi0) : "r"(ux), "r"(uy));
    asm("prmt.b32 %0, %1, %2, 0x7632;" : "=r"(hi1) : "r"(uz), "r"(uw));
    float lx = hx - __uint_as_float(ux & 0xFFFF0000u);
    float ly = hy - __uint_as_float(uy & 0xFFFF0000u);
    float lz = hz - __uint_as_float(uz & 0xFFFF0000u);
    float lw = hw - __uint_as_float(uw & 0xFFFF0000u);
    asm("cvt.rn.bf16x2.f32 %0, %1, %2;" : "=r"(lo0) : "f"(ly), "f"(lx));
    asm("cvt.rn.bf16x2.f32 %0, %1, %2;" : "=r"(lo1) : "f"(lw), "f"(lz));
    size_t off = (size_t)(gw >> 7) * TILEB + (gw & 127) * 272 + lane * 8;
    *(uint2*)(g_h0img_hi + off) = make_uint2(hi0, hi1);
    *(uint2*)(g_h0img_lo + off) = make_uint2(lo0, lo1);
}

// ---------------- GEMM1 (persistent, 512 thr, 16 warps): h1 = h0 @ W1 + b1 ---
#define G1_AHI  0
#define G1_ALO  34816
#define G1_BHI  69632
#define G1_BLO  139264
#define G1_BIAS 208896
#define G1_SMEM 209920

__global__ __launch_bounds__(512) void gemm1_mma(const float* __restrict__ b1, int M, int nb) {
    extern __shared__ char smem[];
    uint32_t sb = smem_u32(smem);
    int tid = threadIdx.x, w = tid >> 5, lane = tid & 31;
    float* b1s = (float*)(smem + G1_BIAS);
    if (tid < 256) b1s[tid] = __ldg(&b1[tid]);

    for (int u = tid; u < 4352; u += 512) {
        CP_ASYNC16(sb + G1_BHI + u * 16, (const char*)g_W1img_hi + u * 16);
        CP_ASYNC16(sb + G1_BLO + u * 16, (const char*)g_W1img_lo + u * 16);
    }
    {
        size_t abase = (size_t)blockIdx.x * TILEB;
        for (int u = tid; u < 2176; u += 512) {
            CP_ASYNC16(sb + G1_AHI + u * 16, (const char*)g_h0img_hi + abase + u * 16);
            CP_ASYNC16(sb + G1_ALO + u * 16, (const char*)g_h0img_lo + abase + u * 16);
        }
    }
    CP_COMMIT();

    // warp tile: 64 rows x 32 cols; w&1 -> m half, w>>1 -> one of 8 n-groups
    int m0 = (w & 1) * 64, n0 = (w >> 1) * 32;
    int lr = lane & 7, mid = lane >> 3;
    uint32_t aoff = (uint32_t)((m0 + lr + ((mid & 1) << 3)) * 272 + ((mid >> 1) << 4));
    uint32_t boff = (uint32_t)((n0 + lr + ((mid >> 1) << 3)) * 272 + ((mid & 1) << 4));
    uint32_t aHb = sb + G1_AHI + aoff, aLb = sb + G1_ALO + aoff;
    uint32_t bHb = sb + G1_BHI + boff, bLb = sb + G1_BLO + boff;

    for (int rb = blockIdx.x; rb < nb; rb += gridDim.x) {
        int row0 = rb * 128;
        CP_WAIT0();
        __syncthreads();

        float acc[4][4][4];
        #pragma unroll
        for (int i = 0; i < 4; i++)
            #pragma unroll
            for (int j = 0; j < 4; j++)
                #pragma unroll
                for (int q = 0; q < 4; q++) acc[i][j][q] = 0.f;

        #pragma unroll
        for (int ks = 0; ks < 8; ks++) {
            uint32_t kb = ks << 5;
            uint32_t aH[4][4], aL[4][4];
            #pragma unroll
            for (int mb = 0; mb < 4; mb++) {
                ldsm_x4(aH[mb], aHb + mb * 4352 + kb);
                ldsm_x4(aL[mb], aLb + mb * 4352 + kb);
            }
            #pragma unroll
            for (int nbp = 0; nbp < 2; nbp++) {
                uint32_t bh[4], bl[4];
                ldsm_x4(bh, bHb + nbp * 4352 + kb);
                ldsm_x4(bl, bLb + nbp * 4352 + kb);
                #pragma unroll
                for (int mb = 0; mb < 4; mb++) {
                    mma16816(acc[mb][2*nbp],     aH[mb], bh);
                    mma16816(acc[mb][2*nbp],     aH[mb], bl);
                    mma16816(acc[mb][2*nbp],     aL[mb], bh);
                    mma16816(acc[mb][2*nbp + 1], aH[mb], bh + 2);
                    mma16816(acc[mb][2*nbp + 1], aH[mb], bl + 2);
                    mma16816(acc[mb][2*nbp + 1], aL[mb], bh + 2);
                }
            }
        }
        __syncthreads();

        int rbn = rb + gridDim.x;
        if (rbn < nb) {
            size_t abase = (size_t)rbn * TILEB;
            for (int u = tid; u < 2176; u += 512) {
                CP_ASYNC16(sb + G1_AHI + u * 16, (const char*)g_h0img_hi + abase + u * 16);
                CP_ASYNC16(sb + G1_ALO + u * 16, (const char*)g_h0img_lo + abase + u * 16);
            }
        }
        CP_COMMIT();

        int mtop = row0 + m0 + (lane >> 2);
        int nc = n0 + 2 * (lane & 3);
        float cs[4][2], cq[4][2];
        #pragma unroll
        for (int j = 0; j < 4; j++) { cs[j][0] = cs[j][1] = cq[j][0] = cq[j][1] = 0.f; }
        #pragma unroll
        for (int mb = 0; mb < 4; mb++) {
            int r0 = mtop + mb * 16;
            bool gd0 = r0 < M, gd1 = (r0 + 8) < M;
            #pragma unroll
            for (int nbq = 0; nbq < 4; nbq++) {
                int n = nc + nbq * 8;
                float bv0 = b1s[n], bv1 = b1s[n + 1];
                float o0 = acc[mb][nbq][0] + bv0, o1 = acc[mb][nbq][1] + bv1;
                float o2 = acc[mb][nbq][2] + bv0, o3 = acc[mb][nbq][3] + bv1;
                size_t r1 = (size_t)r0 * 256 + n;
                *(float2*)(g_h1 + r1)           = make_float2(o0, o1);
                *(float2*)(g_h1 + r1 + 8 * 256) = make_float2(o2, o3);
                cs[nbq][0] += (gd0 ? o0 : 0.f) + (gd1 ? o2 : 0.f);
                cs[nbq][1] += (gd0 ? o1 : 0.f) + (gd1 ? o3 : 0.f);
                cq[nbq][0] += (gd0 ? o0 * o0 : 0.f) + (gd1 ? o2 * o2 : 0.f);
                cq[nbq][1] += (gd0 ? o1 * o1 : 0.f) + (gd1 ? o3 * o3 : 0.f);
            }
        }
        #pragma unroll
        for (int nbq = 0; nbq < 4; nbq++) {
            #pragma unroll
            for (int o = 16; o >= 4; o >>= 1) {
                cs[nbq][0] += __shfl_down_sync(0xffffffffu, cs[nbq][0], o);
                cs[nbq][1] += __shfl_down_sync(0xffffffffu, cs[nbq][1], o);
                cq[nbq][0] += __shfl_down_sync(0xffffffffu, cq[nbq][0], o);
                cq[nbq][1] += __shfl_down_sync(0xffffffffu, cq[nbq][1], o);
            }
        }
        if (lane < 4) {
            #pragma unroll
            for (int nbq = 0; nbq < 4; nbq++) {
                int ncol = n0 + nbq * 8 + 2 * lane;
                atomicAdd(&g_colsum[ncol],     cs[nbq][0]);
                atomicAdd(&g_colsum[ncol + 1], cs[nbq][1]);
                atomicAdd(&g_colsq[ncol],      cq[nbq][0]);
                atomicAdd(&g_colsq[ncol + 1],  cq[nbq][1]);
            }
        }
    }
}

// ---------------- BN finalize ------------------------------------------------
__global__ void bnfinal_kernel(const float* __restrict__ gamma,
                               const float* __restrict__ beta, int n) {
    int c = threadIdx.x;  // 256
    float inv_n = 1.f / (float)n;
    float mu  = g_colsum[c] * inv_n;
    float var = g_colsq[c] * inv_n - mu * mu;
    float sc  = gamma[c] * rsqrtf(var + BN_EPS);
    g_bnscale[c] = sc;
    g_bnshift[c] = beta[c] - mu * sc;
    g_colsum[c] = 0.f;
    g_colsq[c]  = 0.f;
}

// ---------------- GEMM2 (persistent, 512 thr, 16 warps) ----------------------
#define G2_AHI   0
#define G2_ALO   34816
#define G2_B     69632
#define G2_CST   0
#define G2_CONST 208896
#define G2_SMEM  212480

__global__ __launch_bounds__(512) void gemm2_mma(const float* __restrict__ b2,
                                                 const float* __restrict__ ln_gamma,
                                                 const float* __restrict__ ln_beta,
                                                 const float* __restrict__ x,
                                                 float* __restrict__ out, int M, int nb) {
    extern __shared__ char smem[];
    uint32_t sb = smem_u32(smem);
    int tid = threadIdx.x, w = tid >> 5, lane = tid & 31;

    float* s_sc = (float*)(smem + G2_CONST);
    float* s_sh = s_sc + 256;
    float* s_b2 = s_sh + 256;
    float* s_lg = s_b2 + 128;
    float* s_lb = s_lg + 128;
    if (tid < 256) { s_sc[tid] = g_bnscale[tid]; s_sh[tid] = g_bnshift[tid]; }
    if (tid < 128) {
        s_b2[tid] = __ldg(&b2[tid]);
        s_lg[tid] = __ldg(&ln_gamma[tid]);
        s_lb[tid] = __ldg(&ln_beta[tid]);
    }
    for (int u = tid; u < 2176; u += 512) {
        #pragma unroll
        for (int p = 0; p < 2; p++) {
            CP_ASYNC16(sb + G2_B + p * 69632 + u * 16,         (const char*)g_W2img_hi + p * TILEB + u * 16);
            CP_ASYNC16(sb + G2_B + p * 69632 + 34816 + u * 16, (const char*)g_W2img_lo + p * TILEB + u * 16);
        }
    }
    CP_COMMIT();

    // warp tile: 64 rows x 16 cols; w&1 -> m half, w>>1 -> one of 8 n-groups
    int m0 = (w & 1) * 64, n0 = (w >> 1) * 16;
    int lr = lane & 7, mid = lane >> 3;
    uint32_t aoff = (uint32_t)((m0 + lr + ((mid & 1) << 3)) * 272 + ((mid >> 1) << 4));
    uint32_t boff = (uint32_t)((n0 + lr + ((mid >> 1) << 3)) * 272 + ((mid & 1) << 4));
    uint32_t aHb = sb + G2_AHI + aoff, aLb = sb + G2_ALO + aoff;

    for (int rb = blockIdx.x; rb < nb; rb += gridDim.x) {
        int row0 = rb * 128;
        float acc[4][2][4];
        #pragma unroll
        for (int i = 0; i < 4; i++)
            #pragma unroll
            for (int j = 0; j < 2; j++)
                #pragma unroll
                for (int q = 0; q < 4; q++) acc[i][j][q] = 0.f;

        for (int p = 0; p < 2; p++) {
            __syncthreads();
            for (int u = tid; u < 2048; u += 512) {
                int m = u >> 4, g = u & 15;
                int kc = (p << 7) + (g << 3);
                const float4* hr = (const float4*)(g_h1 + (size_t)(row0 + m) * 256 + kc);
                float4 q0 = hr[0], q1 = hr[1];
                float f[8] = {q0.x, q0.y, q0.z, q0.w, q1.x, q1.y, q1.z, q1.w};
                #pragma unroll
                for (int j = 0; j < 8; j++)
                    f[j] = fmaxf(fmaf(f[j], s_sc[kc + j], s_sh[kc + j]), 0.f);
                uint4 hv, lv; cvt8(f, hv, lv);
                int off = m * 272 + g * 16;
                *(uint4*)(smem + G2_AHI + off) = hv;
                *(uint4*)(smem + G2_ALO + off) = lv;
            }
            CP_WAIT0();
            __syncthreads();

            uint32_t bHb = sb + G2_B + p * 69632 + boff;
            uint32_t bLb = bHb + 34816;
            #pragma unroll
            for (int ks = 0; ks < 8; ks++) {
                uint32_t kb = ks << 5;
                uint32_t aH[4][4], aL[4][4];
                #pragma unroll
                for (int mb = 0; mb < 4; mb++) {
                    ldsm_x4(aH[mb], aHb + mb * 4352 + kb);
                    ldsm_x4(aL[mb], aLb + mb * 4352 + kb);
                }
                uint32_t bh[4], bl[4];
                ldsm_x4(bh, bHb + kb);
                ldsm_x4(bl, bLb + kb);
                #pragma unroll
                for (int mb = 0; mb < 4; mb++) {
                    mma16816(acc[mb][0], aH[mb], bh);
                    mma16816(acc[mb][0], aH[mb], bl);
                    mma16816(acc[mb][0], aL[mb], bh);
                    mma16816(acc[mb][1], aH[mb], bh + 2);
                    mma16816(acc[mb][1], aH[mb], bl + 2);
                    mma16816(acc[mb][1], aL[mb], bh + 2);
                }
            }
        }
        __syncthreads();

        float* Cs = (float*)(smem + G2_CST);
        {
            int mtop = m0 + (lane >> 2), nc = n0 + 2 * (lane & 3);
            #pragma unroll
            for (int mb = 0; mb < 4; mb++) {
                #pragma unroll
                for (int nbq = 0; nbq < 2; nbq++) {
                    int n = nc + nbq * 8;
                    int rr = mtop + mb * 16;
                    *(float2*)(Cs + rr * 132 + n)       = make_float2(acc[mb][nbq][0], acc[mb][nbq][1]);
                    *(float2*)(Cs + (rr + 8) * 132 + n) = make_float2(acc[mb][nbq][2], acc[mb][nbq][3]);
                }
            }
        }
        __syncthreads();

        if (tid < 128) {
            int grow = row0 + tid;
            const float* cr = Cs + tid * 132;
            float sum = 0.f, sq = 0.f;
            #pragma unroll
            for (int c = 0; c < 128; c += 4) {
                float4 q = *(const float4*)(cr + c);
                float v0 = q.x + s_b2[c], v1 = q.y + s_b2[c+1];
                float v2 = q.z + s_b2[c+2], v3 = q.w + s_b2[c+3];
                sum += v0 + v1 + v2 + v3;
                sq  += v0*v0 + v1*v1 + v2*v2 + v3*v3;
            }
            float mu = sum * (1.f / D);
            float var = sq * (1.f / D) - mu * mu;
            float rr = rsqrtf(var + LN_EPS);
            if (grow < M) {
                const float4* xr = (const float4*)(x + (size_t)grow * D);
                float4* po = (float4*)(out + (size_t)grow * D);
                #pragma unroll
                for (int c = 0; c < 128; c += 4) {
                    float4 q = *(const float4*)(cr + c);
                    float4 xv = __ldg(xr + (c >> 2));
                    float4 o;
                    o.x = xv.x + fmaxf((q.x + s_b2[c]   - mu) * rr * s_lg[c]   + s_lb[c],   0.f);
                    o.y = xv.y + fmaxf((q.y + s_b2[c+1] - mu) * rr * s_lg[c+1] + s_lb[c+1], 0.f);
                    o.z = xv.z + fmaxf((q.z + s_b2[c+2] - mu) * rr * s_lg[c+2] + s_lb[c+2], 0.f);
                    o.w = xv.w + fmaxf((q.w + s_b2[c+3] - mu) * rr * s_lg[c+3] + s_lb[c+3], 0.f);
                    po[c >> 2] = o;
                }
            }
        }
    }
}

// ---------------- launcher ---------------------------------------------------
extern "C" void kernel_launch(void* const* d_in, const int* in_sizes, int n_in,
                              void* d_out, int out_size) {
    const float* x        = (const float*)d_in[0];
    const int*   ei       = (const int*)  d_in[1];
    const float* t_ptr    = (const float*)d_in[2];
    const float* W1       = (const float*)d_in[3];
    const float* b1       = (const float*)d_in[4];
    const float* bn_gamma = (const float*)d_in[5];
    const float* bn_beta  = (const float*)d_in[6];
    const float* W2       = (const float*)d_in[7];
    const float* b2       = (const float*)d_in[8];
    const float* ln_gamma = (const float*)d_in[9];
    const float* ln_beta  = (const float*)d_in[10];
    float* out = (float*)d_out;

    int n = in_sizes[0] / D;
    int e = in_sizes[1] / 2;
    const int* src = ei;
    const int* dst = ei + e;
    int nb = (n + 127) / 128;
    int npart = (n + 1023) / 1024;
    int gpers = nb < 152 ? nb : 152;
    int work1 = n * 32;
    if (work1 < e) work1 = e;
    if (work1 < 65536) work1 = 65536;
    int hb = (work1 + 1023) / 1024;

    cudaFuncSetAttribute(gemm1_mma, cudaFuncAttributeMaxDynamicSharedMemorySize, G1_SMEM);
    cudaFuncSetAttribute(gemm2_mma, cudaFuncAttributeMaxDynamicSharedMemorySize, G2_SMEM);

    k1_init_hist<<<hb, 1024>>>(W1, W2, x, t_ptr, dst, e, n, npart);
    scan_scatter<<<npart, 1024>>>(src, dst, e, n, npart);
    agg_kernel<<<(n * 32 + 255) / 256, 256>>>(x, n);
    gemm1_mma<<<gpers, 512, G1_SMEM>>>(b1, n, nb);
    bnfinal_kernel<<<1, D2>>>(bn_gamma, bn_beta, n);
    gemm2_mma<<<gpers, 512, G2_SMEM>>>(b2, ln_gamma, ln_beta, x, out, n, nb);
}

// round 16
// speedup vs baseline: 1.1187x; 1.1187x over previous
#include <cuda_runtime.h>
#include <cuda_bf16.h>
#include <cuda_fp16.h>
#include <math_constants.h>
#include <cstdint>

#define NMAX 50176
#define EMAX 800000
#define D    128
#define D2   256
#define MSG_EPS 1e-7f
#define SM_EPS  1e-16f
#define BN_EPS  1e-5f
#define LN_EPS  1e-5f
#define NPARTMAX 64
#define NBMAX 392
#define TILEB 34816          /* bytes per 128-row fp16 tile image (272B pitch) */

// ---------------- scratch (static device globals; no allocation) -------------
__device__ int   g_deg[NMAX];          // zero at entry (reset by scan_scatter)
__device__ int   g_offs[NMAX + 1];
__device__ int   g_cur[NMAX];
__device__ __align__(16) int g_srcs[EMAX];
__device__ int   g_partoffs[NPARTMAX];
__device__ int   g_done1;              // reset by K1 last block
__device__ int   g_done2;              // reset by K1 thread 0
__device__ float g_h1[(size_t)NMAX * D2];
__device__ float g_colsum[D2];         // zero at entry (reset by bnfinal)
__device__ float g_colsq[D2];
__device__ float g_bnscale[D2];
__device__ float g_bnshift[D2];
__device__ __align__(16) uint32_t g_ew[(size_t)NMAX * D];   // half2(E, W) per feature
__device__ __align__(16) unsigned char g_h0img[(size_t)NBMAX * TILEB];   // fp16
__device__ __align__(16) unsigned char g_W1img[69632];                   // fp16, 256n x 128k
__device__ __align__(16) unsigned char g_W2img[69632];                   // fp16, 2 ph x 128n x 128k

// ---------------- helpers ----------------------------------------------------
__device__ __forceinline__ uint32_t smem_u32(const void* p) {
    uint32_t a;
    asm("{ .reg .u64 t; cvta.to.shared.u64 t, %1; cvt.u32.u64 %0, t; }" : "=r"(a) : "l"(p));
    return a;
}
__device__ __forceinline__ void ldsm_x4(uint32_t* r, uint32_t addr) {
    asm volatile("ldmatrix.sync.aligned.m8n8.x4.shared.b16 {%0,%1,%2,%3}, [%4];"
        : "=r"(r[0]), "=r"(r[1]), "=r"(r[2]), "=r"(r[3]) : "r"(addr));
}
__device__ __forceinline__ void mma16816(float* d, const uint32_t* a, const uint32_t* b) {
    asm volatile(
        "mma.sync.aligned.m16n8k16.row.col.f32.f16.f16.f32 "
        "{%0,%1,%2,%3}, {%4,%5,%6,%7}, {%8,%9}, {%0,%1,%2,%3};"
        : "+f"(d[0]), "+f"(d[1]), "+f"(d[2]), "+f"(d[3])
        : "r"(a[0]), "r"(a[1]), "r"(a[2]), "r"(a[3]), "r"(b[0]), "r"(b[1]));
}
__device__ __forceinline__ float ex2(float x) {
    float r;
    asm("ex2.approx.f32 %0, %1;" : "=f"(r) : "f"(x));
    return r;
}
#define CP_ASYNC16(dst_u32, src_ptr) \
    asm volatile("cp.async.cg.shared.global [%0], [%1], 16;" :: "r"(dst_u32), "l"(src_ptr))
#define CP_COMMIT() asm volatile("cp.async.commit_group;")
#define CP_WAIT0()  asm volatile("cp.async.wait_group 0;")

__device__ __forceinline__ uint32_t packEW(float xv, float c) {
    float v = fmaxf(xv, 0.f);
    float e = ex2(v * c);
    __half2 h = __floats2half2_rn(e, e * v);
    return *(uint32_t*)&h;
}
__device__ __forceinline__ uint32_t packh2(float a, float b) {
    __half2 h = __floats2half2_rn(a, b);
    return *(uint32_t*)&h;
}

// ---------------- K1: weight images + EW table + histogram + chunk scan ------
__global__ void k1_init_hist(const float* __restrict__ W1, const float* __restrict__ W2,
                             const float* __restrict__ x, const float* __restrict__ t_ptr,
                             const int* __restrict__ dst, int e, int n, int npart) {
    int i = blockIdx.x * 1024 + threadIdx.x;
    if (i == 0) g_done2 = 0;
    if (i < 32768) {                          // W1^T: n<256, k<128
        int nn = i >> 7, k = i & 127;
        __half h = __float2half(W1[k * 256 + nn]);
        *(unsigned short*)(g_W1img + nn * 272 + k * 2) = *(unsigned short*)&h;
    } else if (i < 65536) {                   // W2^T: n<128, k<256
        int j = i - 32768;
        int nn = j >> 8, k = j & 255;
        __half h = __float2half(W2[k * 128 + nn]);
        *(unsigned short*)(g_W2img + (k >> 7) * TILEB + nn * 272 + (k & 127) * 2) = *(unsigned short*)&h;
    }
    if (i < n * 32) {
        float c = __ldg(t_ptr) * 1.4426950408889634f;
        int node = i >> 5, l = i & 31;
        float4 q = __ldg((const float4*)(x + (size_t)node * D) + l);
        uint4 u;
        u.x = packEW(q.x, c);
        u.y = packEW(q.y, c);
        u.z = packEW(q.z, c);
        u.w = packEW(q.w, c);
        *(uint4*)(g_ew + (size_t)node * D + l * 4) = u;
    }
    if (i < e) atomicAdd(&g_deg[dst[i]], 1);

    __threadfence();
    __shared__ int s_last;
    if (threadIdx.x == 0) s_last = (atomicAdd(&g_done1, 1) == (int)gridDim.x - 1);
    __syncthreads();
    if (!s_last) return;
    if (threadIdx.x == 0) g_done1 = 0;

    __shared__ int csum[NPARTMAX];
    __shared__ int sh[NPARTMAX];
    int t = threadIdx.x, lane = t & 31, w = t >> 5;
    for (int c2 = w; c2 < npart; c2 += 32) {
        int s = 0;
        for (int k = lane; k < 1024; k += 32) {
            int idx = (c2 << 10) + k;
            s += (idx < n) ? g_deg[idx] : 0;
        }
        #pragma unroll
        for (int o = 16; o > 0; o >>= 1) s += __shfl_xor_sync(0xffffffffu, s, o);
        if (lane == 0) csum[c2] = s;
    }
    __syncthreads();
    if (t < NPARTMAX) sh[t] = (t < npart) ? csum[t] : 0;
    __syncthreads();
    for (int o = 1; o < NPARTMAX; o <<= 1) {
        int add = (t < NPARTMAX && t >= o) ? sh[t - o] : 0;
        __syncthreads();
        if (t < NPARTMAX) sh[t] += add;
        __syncthreads();
    }
    if (t < npart) g_partoffs[t] = sh[t] - csum[t];
    if (t == npart - 1) g_offs[n] = sh[t];
}

// ---------------- fused local scan + grid barrier + scatter ------------------
__global__ void scan_scatter(const int* __restrict__ src, const int* __restrict__ dst,
                             int e, int n, int npart) {
    __shared__ int warpsums[32];
    int t = threadIdx.x, lane = t & 31, w = t >> 5;
    int i = blockIdx.x * 1024 + t;
    int v = (i < n) ? g_deg[i] : 0;
    int s = v;
    #pragma unroll
    for (int o = 1; o < 32; o <<= 1) {
        int u = __shfl_up_sync(0xffffffffu, s, o);
        if (lane >= o) s += u;
    }
    if (lane == 31) warpsums[w] = s;
    __syncthreads();
    if (w == 0) {
        int ws = warpsums[lane];
        #pragma unroll
        for (int o = 1; o < 32; o <<= 1) {
            int u = __shfl_up_sync(0xffffffffu, ws, o);
            if (lane >= o) ws += u;
        }
        warpsums[lane] = ws;
    }
    __syncthreads();
    if (i < n) {
        int ex = g_partoffs[blockIdx.x] + s - v + (w > 0 ? warpsums[w - 1] : 0);
        g_offs[i] = ex;
        g_cur[i] = ex;
        g_deg[i] = 0;
    }
    __syncthreads();
    __threadfence();
    if (t == 0) {
        atomicAdd(&g_done2, 1);
        while (atomicAdd(&g_done2, 0) < npart) { __nanosleep(64); }
    }
    __syncthreads();
    for (int j = blockIdx.x * 1024 + t; j < e; j += npart * 1024) {
        int pos = atomicAdd(&g_cur[dst[j]], 1);
        g_srcs[pos] = src[j];
    }
}

// ---------------- one-pass softmax aggregation via EW table ------------------
__device__ __forceinline__ void accEW(uint4 u, float& d0, float& n0, float& d1, float& n1,
                                      float& d2, float& n2, float& d3, float& n3) {
    float2 f;
    f = __half22float2(*(__half2*)&u.x); d0 += f.x; n0 += f.y;
    f = __half22float2(*(__half2*)&u.y); d1 += f.x; n1 += f.y;
    f = __half22float2(*(__half2*)&u.z); d2 += f.x; n2 += f.y;
    f = __half22float2(*(__half2*)&u.w); d3 += f.x; n3 += f.y;
}

__global__ void agg_kernel(const float* __restrict__ x, int n) {
    int gw   = (blockIdx.x * blockDim.x + threadIdx.x) >> 5;
    int lane = threadIdx.x & 31;
    if (gw >= n) return;
    int beg = g_offs[gw], end = g_offs[gw + 1];

    float n0 = 0.f, n1 = 0.f, n2 = 0.f, n3 = 0.f;
    float d0 = 0.f, d1 = 0.f, d2 = 0.f, d3 = 0.f;
    int e = beg;
    while (e < end && (e & 3)) {
        uint4 u = __ldg((const uint4*)(g_ew + (size_t)__ldg(&g_srcs[e]) * D) + lane);
        accEW(u, d0, n0, d1, n1, d2, n2, d3, n3);
        e++;
    }
    int e4 = e + ((end - e) & ~3);
    for (; e < e4; e += 4) {
        int4 s4 = __ldg((const int4*)(g_srcs + e));
        uint4 u0 = __ldg((const uint4*)(g_ew + (size_t)s4.x * D) + lane);
        uint4 u1 = __ldg((const uint4*)(g_ew + (size_t)s4.y * D) + lane);
        uint4 u2 = __ldg((const uint4*)(g_ew + (size_t)s4.z * D) + lane);
        uint4 u3 = __ldg((const uint4*)(g_ew + (size_t)s4.w * D) + lane);
        accEW(u0, d0, n0, d1, n1, d2, n2, d3, n3);
        accEW(u1, d0, n0, d1, n1, d2, n2, d3, n3);
        accEW(u2, d0, n0, d1, n1, d2, n2, d3, n3);
        accEW(u3, d0, n0, d1, n1, d2, n2, d3, n3);
    }
    for (; e < end; e++) {
        uint4 u = __ldg((const uint4*)(g_ew + (size_t)__ldg(&g_srcs[e]) * D) + lane);
        accEW(u, d0, n0, d1, n1, d2, n2, d3, n3);
    }
    float4 xq = __ldg((const float4*)(x + (size_t)gw * D) + lane);
    float hx = (n0 + MSG_EPS * d0) / (d0 + SM_EPS) + xq.x;
    float hy = (n1 + MSG_EPS * d1) / (d1 + SM_EPS) + xq.y;
    float hz = (n2 + MSG_EPS * d2) / (d2 + SM_EPS) + xq.z;
    float hw = (n3 + MSG_EPS * d3) / (d3 + SM_EPS) + xq.w;

    size_t off = (size_t)(gw >> 7) * TILEB + (gw & 127) * 272 + lane * 8;
    *(uint2*)(g_h0img + off) = make_uint2(packh2(hx, hy), packh2(hz, hw));
}

// ---------------- GEMM1 (persistent, fp16 single): h1 = h0 @ W1 + b1 ---------
#define G1_A    0
#define G1_B    34816
#define G1_BIAS 104448
#define G1_SMEM 105472

__global__ __launch_bounds__(256) void gemm1_mma(const float* __restrict__ b1, int M, int nb) {
    extern __shared__ char smem[];
    uint32_t sb = smem_u32(smem);
    int tid = threadIdx.x, w = tid >> 5, lane = tid & 31;
    float* b1s = (float*)(smem + G1_BIAS);
    b1s[tid] = __ldg(&b1[tid]);

    for (int u = tid; u < 4352; u += 256)
        CP_ASYNC16(sb + G1_B + u * 16, (const char*)g_W1img + u * 16);
    {
        size_t abase = (size_t)blockIdx.x * TILEB;
        for (int u = tid; u < 2176; u += 256)
            CP_ASYNC16(sb + G1_A + u * 16, (const char*)g_h0img + abase + u * 16);
    }
    CP_COMMIT();

    int m0 = (w & 1) * 64, n0 = (w >> 1) * 64;
    int lr = lane & 7, mid = lane >> 3;
    uint32_t aoff = (uint32_t)((m0 + lr + ((mid & 1) << 3)) * 272 + ((mid >> 1) << 4));
    uint32_t boff = (uint32_t)((n0 + lr + ((mid >> 1) << 3)) * 272 + ((mid & 1) << 4));
    uint32_t aB = sb + G1_A + aoff;
    uint32_t bB = sb + G1_B + boff;

    for (int rb = blockIdx.x; rb < nb; rb += gridDim.x) {
        int row0 = rb * 128;
        CP_WAIT0();
        __syncthreads();

        float acc[4][8][4];
        #pragma unroll
        for (int i = 0; i < 4; i++)
            #pragma unroll
            for (int j = 0; j < 8; j++)
                #pragma unroll
                for (int q = 0; q < 4; q++) acc[i][j][q] = 0.f;

        #pragma unroll
        for (int ks = 0; ks < 8; ks++) {
            uint32_t kb = ks << 5;
            uint32_t aF[4][4];
            #pragma unroll
            for (int mb = 0; mb < 4; mb++) ldsm_x4(aF[mb], aB + mb * 4352 + kb);
            #pragma unroll
            for (int nbp = 0; nbp < 4; nbp++) {
                uint32_t bh[4];
                ldsm_x4(bh, bB + nbp * 4352 + kb);
                #pragma unroll
                for (int mb = 0; mb < 4; mb++) {
                    mma16816(acc[mb][2*nbp],     aF[mb], bh);
                    mma16816(acc[mb][2*nbp + 1], aF[mb], bh + 2);
                }
            }
        }
        __syncthreads();

        int rbn = rb + gridDim.x;
        if (rbn < nb) {
            size_t abase = (size_t)rbn * TILEB;
            for (int u = tid; u < 2176; u += 256)
                CP_ASYNC16(sb + G1_A + u * 16, (const char*)g_h0img + abase + u * 16);
        }
        CP_COMMIT();

        int mtop = row0 + m0 + (lane >> 2);
        int nc = n0 + 2 * (lane & 3);
        float cs[8][2], cq[8][2];
        #pragma unroll
        for (int j = 0; j < 8; j++) { cs[j][0] = cs[j][1] = cq[j][0] = cq[j][1] = 0.f; }
        #pragma unroll
        for (int mb = 0; mb < 4; mb++) {
            int r0 = mtop + mb * 16;
            bool gd0 = r0 < M, gd1 = (r0 + 8) < M;
            #pragma unroll
            for (int nbq = 0; nbq < 8; nbq++) {
                int n = nc + nbq * 8;
                float bv0 = b1s[n], bv1 = b1s[n + 1];
                float o0 = acc[mb][nbq][0] + bv0, o1 = acc[mb][nbq][1] + bv1;
                float o2 = acc[mb][nbq][2] + bv0, o3 = acc[mb][nbq][3] + bv1;
                size_t r1 = (size_t)r0 * 256 + n;
                *(float2*)(g_h1 + r1)           = make_float2(o0, o1);
                *(float2*)(g_h1 + r1 + 8 * 256) = make_float2(o2, o3);
                cs[nbq][0] += (gd0 ? o0 : 0.f) + (gd1 ? o2 : 0.f);
                cs[nbq][1] += (gd0 ? o1 : 0.f) + (gd1 ? o3 : 0.f);
                cq[nbq][0] += (gd0 ? o0 * o0 : 0.f) + (gd1 ? o2 * o2 : 0.f);
                cq[nbq][1] += (gd0 ? o1 * o1 : 0.f) + (gd1 ? o3 * o3 : 0.f);
            }
        }
        #pragma unroll
        for (int nbq = 0; nbq < 8; nbq++) {
            #pragma unroll
            for (int o = 16; o >= 4; o >>= 1) {
                cs[nbq][0] += __shfl_down_sync(0xffffffffu, cs[nbq][0], o);
                cs[nbq][1] += __shfl_down_sync(0xffffffffu, cs[nbq][1], o);
                cq[nbq][0] += __shfl_down_sync(0xffffffffu, cq[nbq][0], o);
                cq[nbq][1] += __shfl_down_sync(0xffffffffu, cq[nbq][1], o);
            }
        }
        if (lane < 4) {
            #pragma unroll
            for (int nbq = 0; nbq < 8; nbq++) {
                int ncol = n0 + nbq * 8 + 2 * lane;
                atomicAdd(&g_colsum[ncol],     cs[nbq][0]);
                atomicAdd(&g_colsum[ncol + 1], cs[nbq][1]);
                atomicAdd(&g_colsq[ncol],      cq[nbq][0]);
                atomicAdd(&g_colsq[ncol + 1],  cq[nbq][1]);
            }
        }
    }
}

// ---------------- BN finalize ------------------------------------------------
__global__ void bnfinal_kernel(const float* __restrict__ gamma,
                               const float* __restrict__ beta, int n) {
    int c = threadIdx.x;  // 256
    float inv_n = 1.f / (float)n;
    float mu  = g_colsum[c] * inv_n;
    float var = g_colsq[c] * inv_n - mu * mu;
    float sc  = gamma[c] * rsqrtf(var + BN_EPS);
    g_bnscale[c] = sc;
    g_bnshift[c] = beta[c] - mu * sc;
    g_colsum[c] = 0.f;
    g_colsq[c]  = 0.f;
}

// ---------------- GEMM2 (persistent, fp16 single, 2 CTA/SM) ------------------
// smem: A@0 (34816; C-stage 64x132 floats = 33792 reuses it) |
//       B@34816 (2 phases x 34816 = 69632) | consts@104448 (3584) = 108032
#define G2_A     0
#define G2_B     34816
#define G2_CONST 104448
#define G2_SMEM  108032

__global__ __launch_bounds__(256, 2) void gemm2_mma(const float* __restrict__ b2,
                                                    const float* __restrict__ ln_gamma,
                                                    const float* __restrict__ ln_beta,
                                                    const float* __restrict__ x,
                                                    float* __restrict__ out, int M, int nb) {
    extern __shared__ char smem[];
    uint32_t sb = smem_u32(smem);
    int tid = threadIdx.x, w = tid >> 5, lane = tid & 31;

    float* s_sc = (float*)(smem + G2_CONST);
    float* s_sh = s_sc + 256;
    float* s_b2 = s_sh + 256;
    float* s_lg = s_b2 + 128;
    float* s_lb = s_lg + 128;
    s_sc[tid] = g_bnscale[tid];
    s_sh[tid] = g_bnshift[tid];
    if (tid < 128) {
        s_b2[tid] = __ldg(&b2[tid]);
        s_lg[tid] = __ldg(&ln_gamma[tid]);
        s_lb[tid] = __ldg(&ln_beta[tid]);
    }
    for (int u = tid; u < 4352; u += 256)
        CP_ASYNC16(sb + G2_B + u * 16, (const char*)g_W2img + u * 16);
    CP_COMMIT();
    CP_WAIT0();

    int m0 = (w & 1) * 64, n0 = (w >> 1) * 32;
    int lr = lane & 7, mid = lane >> 3;
    uint32_t aoff = (uint32_t)((m0 + lr + ((mid & 1) << 3)) * 272 + ((mid >> 1) << 4));
    uint32_t boff = (uint32_t)((n0 + lr + ((mid >> 1) << 3)) * 272 + ((mid & 1) << 4));
    uint32_t aB = sb + G2_A + aoff;

    for (int rb = blockIdx.x; rb < nb; rb += gridDim.x) {
        int row0 = rb * 128;
        float acc[4][4][4];
        #pragma unroll
        for (int i = 0; i < 4; i++)
            #pragma unroll
            for (int j = 0; j < 4; j++)
                #pragma unroll
                for (int q = 0; q < 4; q++) acc[i][j][q] = 0.f;

        for (int p = 0; p < 2; p++) {
            __syncthreads();   // protect A region (also C-stage) from prior use
            for (int u = tid; u < 2048; u += 256) {
                int m = u >> 4, g = u & 15;
                int kc = (p << 7) + (g << 3);
                const float4* hr = (const float4*)(g_h1 + (size_t)(row0 + m) * 256 + kc);
                float4 q0 = hr[0], q1 = hr[1];
                float f[8] = {q0.x, q0.y, q0.z, q0.w, q1.x, q1.y, q1.z, q1.w};
                #pragma unroll
                for (int j = 0; j < 8; j++)
                    f[j] = fmaxf(fmaf(f[j], s_sc[kc + j], s_sh[kc + j]), 0.f);
                uint4 hv;
                hv.x = packh2(f[0], f[1]);
                hv.y = packh2(f[2], f[3]);
                hv.z = packh2(f[4], f[5]);
                hv.w = packh2(f[6], f[7]);
                *(uint4*)(smem + G2_A + m * 272 + g * 16) = hv;
            }
            __syncthreads();

            uint32_t bB = sb + G2_B + p * TILEB + boff;
            #pragma unroll
            for (int ks = 0; ks < 8; ks++) {
                uint32_t kb = ks << 5;
                uint32_t aF[4][4];
                #pragma unroll
                for (int mb = 0; mb < 4; mb++) ldsm_x4(aF[mb], aB + mb * 4352 + kb);
                #pragma unroll
                for (int nbp = 0; nbp < 2; nbp++) {
                    uint32_t bh[4];
                    ldsm_x4(bh, bB + nbp * 4352 + kb);
                    #pragma unroll
                    for (int mb = 0; mb < 4; mb++) {
                        mma16816(acc[mb][2*nbp],     aF[mb], bh);
                        mma16816(acc[mb][2*nbp + 1], aF[mb], bh + 2);
                    }
                }
            }
        }

        // epilogue in two 64-row halves staged through the A region
        float* Cs = (float*)(smem + G2_A);   // 64 x 132 floats = 33792 B
        #pragma unroll
        for (int hh = 0; hh < 2; hh++) {
            __syncthreads();
            if ((w & 1) == hh) {
                int mloc = lane >> 2, nc = n0 + 2 * (lane & 3);
                #pragma unroll
                for (int mb = 0; mb < 4; mb++) {
                    #pragma unroll
                    for (int nbq = 0; nbq < 4; nbq++) {
                        int n = nc + nbq * 8;
                        int rr = mloc + mb * 16;
                        *(float2*)(Cs + rr * 132 + n)       = make_float2(acc[mb][nbq][0], acc[mb][nbq][1]);
                        *(float2*)(Cs + (rr + 8) * 132 + n) = make_float2(acc[mb][nbq][2], acc[mb][nbq][3]);
                    }
                }
            }
            __syncthreads();
            if (tid < 64) {
                int grow = row0 + hh * 64 + tid;
                const float* cr = Cs + tid * 132;
                float sum = 0.f, sq = 0.f;
                #pragma unroll
                for (int c = 0; c < 128; c += 4) {
                    float4 q = *(const float4*)(cr + c);
                    float v0 = q.x + s_b2[c], v1 = q.y + s_b2[c+1];
                    float v2 = q.z + s_b2[c+2], v3 = q.w + s_b2[c+3];
                    sum += v0 + v1 + v2 + v3;
                    sq  += v0*v0 + v1*v1 + v2*v2 + v3*v3;
                }
                float mu = sum * (1.f / D);
                float var = sq * (1.f / D) - mu * mu;
                float rr = rsqrtf(var + LN_EPS);
                if (grow < M) {
                    const float4* xr = (const float4*)(x + (size_t)grow * D);
                    float4* po = (float4*)(out + (size_t)grow * D);
                    #pragma unroll
                    for (int c = 0; c < 128; c += 4) {
                        float4 q = *(const float4*)(cr + c);
                        float4 xv = __ldg(xr + (c >> 2));
                        float4 o;
                        o.x = xv.x + fmaxf((q.x + s_b2[c]   - mu) * rr * s_lg[c]   + s_lb[c],   0.f);
                        o.y = xv.y + fmaxf((q.y + s_b2[c+1] - mu) * rr * s_lg[c+1] + s_lb[c+1], 0.f);
                        o.z = xv.z + fmaxf((q.z + s_b2[c+2] - mu) * rr * s_lg[c+2] + s_lb[c+2], 0.f);
                        o.w = xv.w + fmaxf((q.w + s_b2[c+3] - mu) * rr * s_lg[c+3] + s_lb[c+3], 0.f);
                        po[c >> 2] = o;
                    }
                }
            }
        }
    }
}

// ---------------- launcher ---------------------------------------------------
extern "C" void kernel_launch(void* const* d_in, const int* in_sizes, int n_in,
                              void* d_out, int out_size) {
    const float* x        = (const float*)d_in[0];
    const int*   ei       = (const int*)  d_in[1];
    const float* t_ptr    = (const float*)d_in[2];
    const float* W1       = (const float*)d_in[3];
    const float* b1       = (const float*)d_in[4];
    const float* bn_gamma = (const float*)d_in[5];
    const float* bn_beta  = (const float*)d_in[6];
    const float* W2       = (const float*)d_in[7];
    const float* b2       = (const float*)d_in[8];
    const float* ln_gamma = (const float*)d_in[9];
    const float* ln_beta  = (const float*)d_in[10];
    float* out = (float*)d_out;

    int n = in_sizes[0] / D;
    int e = in_sizes[1] / 2;
    const int* src = ei;
    const int* dst = ei + e;
    int nb = (n + 127) / 128;
    int npart = (n + 1023) / 1024;
    int gp1 = nb < 152 ? nb : 152;
    int gp2 = nb < 304 ? nb : 304;
    int work1 = n * 32;
    if (work1 < e) work1 = e;
    if (work1 < 65536) work1 = 65536;
    int hb = (work1 + 1023) / 1024;

    cudaFuncSetAttribute(gemm1_mma, cudaFuncAttributeMaxDynamicSharedMemorySize, G1_SMEM);
    cudaFuncSetAttribute(gemm2_mma, cudaFuncAttributeMaxDynamicSharedMemorySize, G2_SMEM);

    k1_init_hist<<<hb, 1024>>>(W1, W2, x, t_ptr, dst, e, n, npart);
    scan_scatter<<<npart, 1024>>>(src, dst, e, n, npart);
    agg_kernel<<<(n * 32 + 255) / 256, 256>>>(x, n);
    gemm1_mma<<<gp1, 256, G1_SMEM>>>(b1, n, nb);
    bnfinal_kernel<<<1, D2>>>(bn_gamma, bn_beta, n);
    gemm2_mma<<<gp2, 256, G2_SMEM>>>(b2, ln_gamma, ln_beta, x, out, n, nb);
}

// round 17
// speedup vs baseline: 1.1360x; 1.0154x over previous
#include <cuda_runtime.h>
#include <cuda_bf16.h>
#include <cuda_fp16.h>
#include <math_constants.h>
#include <cstdint>

#define NMAX 50176
#define EMAX 800000
#define D    128
#define D2   256
#define MSG_EPS 1e-7f
#define SM_EPS  1e-16f
#define BN_EPS  1e-5f
#define LN_EPS  1e-5f
#define NPARTMAX 64
#define NBMAX 392
#define TILEB 34816          /* bytes per 128-row fp16 tile image (272B pitch) */

// ---------------- scratch (static device globals; no allocation) -------------
__device__ int   g_deg[NMAX];          // zero at entry (reset by scan_scatter)
__device__ int   g_offs[NMAX + 1];
__device__ int   g_cur[NMAX];
__device__ __align__(16) int g_srcs[EMAX];
__device__ int   g_partoffs[NPARTMAX];
__device__ int   g_done1;              // reset by K1 last block
__device__ int   g_done2;              // reset by K1 thread 0
__device__ __align__(16) __half g_h1[(size_t)NMAX * D2];   // fp16 intermediate
__device__ float g_colsum[D2];         // zero at entry (reset by bnfinal)
__device__ float g_colsq[D2];
__device__ float g_bnscale[D2];
__device__ float g_bnshift[D2];
__device__ __align__(16) uint32_t g_ew[(size_t)NMAX * D];   // half2(E, W) per feature
__device__ __align__(16) unsigned char g_h0img[(size_t)NBMAX * TILEB];   // fp16
__device__ __align__(16) unsigned char g_W1img[69632];                   // fp16, 256n x 128k
__device__ __align__(16) unsigned char g_W2img[69632];                   // fp16, 2 ph x 128n x 128k

// ---------------- helpers ----------------------------------------------------
__device__ __forceinline__ uint32_t smem_u32(const void* p) {
    uint32_t a;
    asm("{ .reg .u64 t; cvta.to.shared.u64 t, %1; cvt.u32.u64 %0, t; }" : "=r"(a) : "l"(p));
    return a;
}
__device__ __forceinline__ void ldsm_x4(uint32_t* r, uint32_t addr) {
    asm volatile("ldmatrix.sync.aligned.m8n8.x4.shared.b16 {%0,%1,%2,%3}, [%4];"
        : "=r"(r[0]), "=r"(r[1]), "=r"(r[2]), "=r"(r[3]) : "r"(addr));
}
__device__ __forceinline__ void mma16816(float* d, const uint32_t* a, const uint32_t* b) {
    asm volatile(
        "mma.sync.aligned.m16n8k16.row.col.f32.f16.f16.f32 "
        "{%0,%1,%2,%3}, {%4,%5,%6,%7}, {%8,%9}, {%0,%1,%2,%3};"
        : "+f"(d[0]), "+f"(d[1]), "+f"(d[2]), "+f"(d[3])
        : "r"(a[0]), "r"(a[1]), "r"(a[2]), "r"(a[3]), "r"(b[0]), "r"(b[1]));
}
__device__ __forceinline__ float ex2(float x) {
    float r;
    asm("ex2.approx.f32 %0, %1;" : "=f"(r) : "f"(x));
    return r;
}
#define CP_ASYNC16(dst_u32, src_ptr) \
    asm volatile("cp.async.cg.shared.global [%0], [%1], 16;" :: "r"(dst_u32), "l"(src_ptr))
#define CP_COMMIT() asm volatile("cp.async.commit_group;")
#define CP_WAIT0()  asm volatile("cp.async.wait_group 0;")

__device__ __forceinline__ uint32_t packEW(float xv, float c) {
    float v = fmaxf(xv, 0.f);
    float e = ex2(v * c);
    __half2 h = __floats2half2_rn(e, e * v);
    return *(uint32_t*)&h;
}
__device__ __forceinline__ uint32_t packh2(float a, float b) {
    __half2 h = __floats2half2_rn(a, b);
    return *(uint32_t*)&h;
}

// ---------------- K1: weight images + EW table + histogram + chunk scan ------
__global__ void k1_init_hist(const float* __restrict__ W1, const float* __restrict__ W2,
                             const float* __restrict__ x, const float* __restrict__ t_ptr,
                             const int* __restrict__ dst, int e, int n, int npart) {
    int i = blockIdx.x * 1024 + threadIdx.x;
    if (i == 0) g_done2 = 0;
    if (i < 32768) {                          // W1^T: n<256, k<128
        int nn = i >> 7, k = i & 127;
        __half h = __float2half(W1[k * 256 + nn]);
        *(unsigned short*)(g_W1img + nn * 272 + k * 2) = *(unsigned short*)&h;
    } else if (i < 65536) {                   // W2^T: n<128, k<256
        int j = i - 32768;
        int nn = j >> 8, k = j & 255;
        __half h = __float2half(W2[k * 128 + nn]);
        *(unsigned short*)(g_W2img + (k >> 7) * TILEB + nn * 272 + (k & 127) * 2) = *(unsigned short*)&h;
    }
    if (i < n * 32) {
        float c = __ldg(t_ptr) * 1.4426950408889634f;
        int node = i >> 5, l = i & 31;
        float4 q = __ldg((const float4*)(x + (size_t)node * D) + l);
        uint4 u;
        u.x = packEW(q.x, c);
        u.y = packEW(q.y, c);
        u.z = packEW(q.z, c);
        u.w = packEW(q.w, c);
        *(uint4*)(g_ew + (size_t)node * D + l * 4) = u;
    }
    if (i < e) atomicAdd(&g_deg[dst[i]], 1);

    __threadfence();
    __shared__ int s_last;
    if (threadIdx.x == 0) s_last = (atomicAdd(&g_done1, 1) == (int)gridDim.x - 1);
    __syncthreads();
    if (!s_last) return;
    if (threadIdx.x == 0) g_done1 = 0;

    __shared__ int csum[NPARTMAX];
    __shared__ int sh[NPARTMAX];
    int t = threadIdx.x, lane = t & 31, w = t >> 5;
    for (int c2 = w; c2 < npart; c2 += 32) {
        int s = 0;
        for (int k = lane; k < 1024; k += 32) {
            int idx = (c2 << 10) + k;
            s += (idx < n) ? g_deg[idx] : 0;
        }
        #pragma unroll
        for (int o = 16; o > 0; o >>= 1) s += __shfl_xor_sync(0xffffffffu, s, o);
        if (lane == 0) csum[c2] = s;
    }
    __syncthreads();
    if (t < NPARTMAX) sh[t] = (t < npart) ? csum[t] : 0;
    __syncthreads();
    for (int o = 1; o < NPARTMAX; o <<= 1) {
        int add = (t < NPARTMAX && t >= o) ? sh[t - o] : 0;
        __syncthreads();
        if (t < NPARTMAX) sh[t] += add;
        __syncthreads();
    }
    if (t < npart) g_partoffs[t] = sh[t] - csum[t];
    if (t == npart - 1) g_offs[n] = sh[t];
}

// ---------------- fused local scan + grid barrier + scatter ------------------
__global__ void scan_scatter(const int* __restrict__ src, const int* __restrict__ dst,
                             int e, int n, int npart) {
    __shared__ int warpsums[32];
    int t = threadIdx.x, lane = t & 31, w = t >> 5;
    int i = blockIdx.x * 1024 + t;
    int v = (i < n) ? g_deg[i] : 0;
    int s = v;
    #pragma unroll
    for (int o = 1; o < 32; o <<= 1) {
        int u = __shfl_up_sync(0xffffffffu, s, o);
        if (lane >= o) s += u;
    }
    if (lane == 31) warpsums[w] = s;
    __syncthreads();
    if (w == 0) {
        int ws = warpsums[lane];
        #pragma unroll
        for (int o = 1; o < 32; o <<= 1) {
            int u = __shfl_up_sync(0xffffffffu, ws, o);
            if (lane >= o) ws += u;
        }
        warpsums[lane] = ws;
    }
    __syncthreads();
    if (i < n) {
        int ex = g_partoffs[blockIdx.x] + s - v + (w > 0 ? warpsums[w - 1] : 0);
        g_offs[i] = ex;
        g_cur[i] = ex;
        g_deg[i] = 0;
    }
    __syncthreads();
    __threadfence();
    if (t == 0) {
        atomicAdd(&g_done2, 1);
        while (atomicAdd(&g_done2, 0) < npart) { __nanosleep(64); }
    }
    __syncthreads();
    for (int j = blockIdx.x * 1024 + t; j < e; j += npart * 1024) {
        int pos = atomicAdd(&g_cur[dst[j]], 1);
        g_srcs[pos] = src[j];
    }
}

// ---------------- one-pass softmax aggregation via EW table ------------------
__device__ __forceinline__ void accEW(uint4 u, float& d0, float& n0, float& d1, float& n1,
                                      float& d2, float& n2, float& d3, float& n3) {
    float2 f;
    f = __half22float2(*(__half2*)&u.x); d0 += f.x; n0 += f.y;
    f = __half22float2(*(__half2*)&u.y); d1 += f.x; n1 += f.y;
    f = __half22float2(*(__half2*)&u.z); d2 += f.x; n2 += f.y;
    f = __half22float2(*(__half2*)&u.w); d3 += f.x; n3 += f.y;
}

__global__ void agg_kernel(const float* __restrict__ x, int n) {
    int gw   = (blockIdx.x * blockDim.x + threadIdx.x) >> 5;
    int lane = threadIdx.x & 31;
    if (gw >= n) return;
    int beg = g_offs[gw], end = g_offs[gw + 1];

    float n0 = 0.f, n1 = 0.f, n2 = 0.f, n3 = 0.f;
    float d0 = 0.f, d1 = 0.f, d2 = 0.f, d3 = 0.f;
    int e = beg;
    while (e < end && (e & 3)) {
        uint4 u = __ldg((const uint4*)(g_ew + (size_t)__ldg(&g_srcs[e]) * D) + lane);
        accEW(u, d0, n0, d1, n1, d2, n2, d3, n3);
        e++;
    }
    int e4 = e + ((end - e) & ~3);
    for (; e < e4; e += 4) {
        int4 s4 = __ldg((const int4*)(g_srcs + e));
        uint4 u0 = __ldg((const uint4*)(g_ew + (size_t)s4.x * D) + lane);
        uint4 u1 = __ldg((const uint4*)(g_ew + (size_t)s4.y * D) + lane);
        uint4 u2 = __ldg((const uint4*)(g_ew + (size_t)s4.z * D) + lane);
        uint4 u3 = __ldg((const uint4*)(g_ew + (size_t)s4.w * D) + lane);
        accEW(u0, d0, n0, d1, n1, d2, n2, d3, n3);
        accEW(u1, d0, n0, d1, n1, d2, n2, d3, n3);
        accEW(u2, d0, n0, d1, n1, d2, n2, d3, n3);
        accEW(u3, d0, n0, d1, n1, d2, n2, d3, n3);
    }
    for (; e < end; e++) {
        uint4 u = __ldg((const uint4*)(g_ew + (size_t)__ldg(&g_srcs[e]) * D) + lane);
        accEW(u, d0, n0, d1, n1, d2, n2, d3, n3);
    }
    float4 xq = __ldg((const float4*)(x + (size_t)gw * D) + lane);
    float hx = (n0 + MSG_EPS * d0) / (d0 + SM_EPS) + xq.x;
    float hy = (n1 + MSG_EPS * d1) / (d1 + SM_EPS) + xq.y;
    float hz = (n2 + MSG_EPS * d2) / (d2 + SM_EPS) + xq.z;
    float hw = (n3 + MSG_EPS * d3) / (d3 + SM_EPS) + xq.w;

    size_t off = (size_t)(gw >> 7) * TILEB + (gw & 127) * 272 + lane * 8;
    *(uint2*)(g_h0img + off) = make_uint2(packh2(hx, hy), packh2(hz, hw));
}

// ---------------- GEMM1 (persistent, fp16 single): h1 = h0 @ W1 + b1 ---------
#define G1_A    0
#define G1_B    34816
#define G1_BIAS 104448
#define G1_SMEM 105472

__global__ __launch_bounds__(256) void gemm1_mma(const float* __restrict__ b1, int M, int nb) {
    extern __shared__ char smem[];
    uint32_t sb = smem_u32(smem);
    int tid = threadIdx.x, w = tid >> 5, lane = tid & 31;
    float* b1s = (float*)(smem + G1_BIAS);
    b1s[tid] = __ldg(&b1[tid]);

    for (int u = tid; u < 4352; u += 256)
        CP_ASYNC16(sb + G1_B + u * 16, (const char*)g_W1img + u * 16);
    {
        size_t abase = (size_t)blockIdx.x * TILEB;
        for (int u = tid; u < 2176; u += 256)
            CP_ASYNC16(sb + G1_A + u * 16, (const char*)g_h0img + abase + u * 16);
    }
    CP_COMMIT();

    int m0 = (w & 1) * 64, n0 = (w >> 1) * 64;
    int lr = lane & 7, mid = lane >> 3;
    uint32_t aoff = (uint32_t)((m0 + lr + ((mid & 1) << 3)) * 272 + ((mid >> 1) << 4));
    uint32_t boff = (uint32_t)((n0 + lr + ((mid >> 1) << 3)) * 272 + ((mid & 1) << 4));
    uint32_t aB = sb + G1_A + aoff;
    uint32_t bB = sb + G1_B + boff;

    for (int rb = blockIdx.x; rb < nb; rb += gridDim.x) {
        int row0 = rb * 128;
        CP_WAIT0();
        __syncthreads();

        float acc[4][8][4];
        #pragma unroll
        for (int i = 0; i < 4; i++)
            #pragma unroll
            for (int j = 0; j < 8; j++)
                #pragma unroll
                for (int q = 0; q < 4; q++) acc[i][j][q] = 0.f;

        #pragma unroll
        for (int ks = 0; ks < 8; ks++) {
            uint32_t kb = ks << 5;
            uint32_t aF[4][4];
            #pragma unroll
            for (int mb = 0; mb < 4; mb++) ldsm_x4(aF[mb], aB + mb * 4352 + kb);
            #pragma unroll
            for (int nbp = 0; nbp < 4; nbp++) {
                uint32_t bh[4];
                ldsm_x4(bh, bB + nbp * 4352 + kb);
                #pragma unroll
                for (int mb = 0; mb < 4; mb++) {
                    mma16816(acc[mb][2*nbp],     aF[mb], bh);
                    mma16816(acc[mb][2*nbp + 1], aF[mb], bh + 2);
                }
            }
        }
        __syncthreads();

        int rbn = rb + gridDim.x;
        if (rbn < nb) {
            size_t abase = (size_t)rbn * TILEB;
            for (int u = tid; u < 2176; u += 256)
                CP_ASYNC16(sb + G1_A + u * 16, (const char*)g_h0img + abase + u * 16);
        }
        CP_COMMIT();

        int mtop = row0 + m0 + (lane >> 2);
        int nc = n0 + 2 * (lane & 3);
        float cs[8][2], cq[8][2];
        #pragma unroll
        for (int j = 0; j < 8; j++) { cs[j][0] = cs[j][1] = cq[j][0] = cq[j][1] = 0.f; }
        #pragma unroll
        for (int mb = 0; mb < 4; mb++) {
            int r0 = mtop + mb * 16;
            bool gd0 = r0 < M, gd1 = (r0 + 8) < M;
            #pragma unroll
            for (int nbq = 0; nbq < 8; nbq++) {
                int n = nc + nbq * 8;
                float bv0 = b1s[n], bv1 = b1s[n + 1];
                float o0 = acc[mb][nbq][0] + bv0, o1 = acc[mb][nbq][1] + bv1;
                float o2 = acc[mb][nbq][2] + bv0, o3 = acc[mb][nbq][3] + bv1;
                size_t r1 = (size_t)r0 * 256 + n;
                *(uint32_t*)(g_h1 + r1)           = packh2(o0, o1);
                *(uint32_t*)(g_h1 + r1 + 8 * 256) = packh2(o2, o3);
                cs[nbq][0] += (gd0 ? o0 : 0.f) + (gd1 ? o2 : 0.f);
                cs[nbq][1] += (gd0 ? o1 : 0.f) + (gd1 ? o3 : 0.f);
                cq[nbq][0] += (gd0 ? o0 * o0 : 0.f) + (gd1 ? o2 * o2 : 0.f);
                cq[nbq][1] += (gd0 ? o1 * o1 : 0.f) + (gd1 ? o3 * o3 : 0.f);
            }
        }
        #pragma unroll
        for (int nbq = 0; nbq < 8; nbq++) {
            #pragma unroll
            for (int o = 16; o >= 4; o >>= 1) {
                cs[nbq][0] += __shfl_down_sync(0xffffffffu, cs[nbq][0], o);
                cs[nbq][1] += __shfl_down_sync(0xffffffffu, cs[nbq][1], o);
                cq[nbq][0] += __shfl_down_sync(0xffffffffu, cq[nbq][0], o);
                cq[nbq][1] += __shfl_down_sync(0xffffffffu, cq[nbq][1], o);
            }
        }
        if (lane < 4) {
            #pragma unroll
            for (int nbq = 0; nbq < 8; nbq++) {
                int ncol = n0 + nbq * 8 + 2 * lane;
                atomicAdd(&g_colsum[ncol],     cs[nbq][0]);
                atomicAdd(&g_colsum[ncol + 1], cs[nbq][1]);
                atomicAdd(&g_colsq[ncol],      cq[nbq][0]);
                atomicAdd(&g_colsq[ncol + 1],  cq[nbq][1]);
            }
        }
    }
}

// ---------------- BN finalize ------------------------------------------------
__global__ void bnfinal_kernel(const float* __restrict__ gamma,
                               const float* __restrict__ beta, int n) {
    int c = threadIdx.x;  // 256
    float inv_n = 1.f / (float)n;
    float mu  = g_colsum[c] * inv_n;
    float var = g_colsq[c] * inv_n - mu * mu;
    float sc  = gamma[c] * rsqrtf(var + BN_EPS);
    g_bnscale[c] = sc;
    g_bnshift[c] = beta[c] - mu * sc;
    g_colsum[c] = 0.f;
    g_colsq[c]  = 0.f;
}

// ---------------- GEMM2 (persistent, fp16 single, 2 CTA/SM) ------------------
#define G2_A     0
#define G2_B     34816
#define G2_CONST 104448
#define G2_SMEM  108032

__global__ __launch_bounds__(256, 2) void gemm2_mma(const float* __restrict__ b2,
                                                    const float* __restrict__ ln_gamma,
                                                    const float* __restrict__ ln_beta,
                                                    const float* __restrict__ x,
                                                    float* __restrict__ out, int M, int nb) {
    extern __shared__ char smem[];
    uint32_t sb = smem_u32(smem);
    int tid = threadIdx.x, w = tid >> 5, lane = tid & 31;

    float* s_sc = (float*)(smem + G2_CONST);
    float* s_sh = s_sc + 256;
    float* s_b2 = s_sh + 256;
    float* s_lg = s_b2 + 128;
    float* s_lb = s_lg + 128;
    s_sc[tid] = g_bnscale[tid];
    s_sh[tid] = g_bnshift[tid];
    if (tid < 128) {
        s_b2[tid] = __ldg(&b2[tid]);
        s_lg[tid] = __ldg(&ln_gamma[tid]);
        s_lb[tid] = __ldg(&ln_beta[tid]);
    }
    for (int u = tid; u < 4352; u += 256)
        CP_ASYNC16(sb + G2_B + u * 16, (const char*)g_W2img + u * 16);
    CP_COMMIT();
    CP_WAIT0();

    int m0 = (w & 1) * 64, n0 = (w >> 1) * 32;
    int lr = lane & 7, mid = lane >> 3;
    uint32_t aoff = (uint32_t)((m0 + lr + ((mid & 1) << 3)) * 272 + ((mid >> 1) << 4));
    uint32_t boff = (uint32_t)((n0 + lr + ((mid >> 1) << 3)) * 272 + ((mid & 1) << 4));
    uint32_t aB = sb + G2_A + aoff;

    for (int rb = blockIdx.x; rb < nb; rb += gridDim.x) {
        int row0 = rb * 128;
        float acc[4][4][4];
        #pragma unroll
        for (int i = 0; i < 4; i++)
            #pragma unroll
            for (int j = 0; j < 4; j++)
                #pragma unroll
                for (int q = 0; q < 4; q++) acc[i][j][q] = 0.f;

        for (int p = 0; p < 2; p++) {
            __syncthreads();   // protect A region (also C-stage) from prior use
            for (int u = tid; u < 2048; u += 256) {
                int m = u >> 4, g = u & 15;
                int kc = (p << 7) + (g << 3);
                uint4 hin = __ldg((const uint4*)(g_h1 + (size_t)(row0 + m) * 256 + kc));
                float2 f0 = __half22float2(*(__half2*)&hin.x);
                float2 f1 = __half22float2(*(__half2*)&hin.y);
                float2 f2 = __half22float2(*(__half2*)&hin.z);
                float2 f3 = __half22float2(*(__half2*)&hin.w);
                float f[8] = {f0.x, f0.y, f1.x, f1.y, f2.x, f2.y, f3.x, f3.y};
                #pragma unroll
                for (int j = 0; j < 8; j++)
                    f[j] = fmaxf(fmaf(f[j], s_sc[kc + j], s_sh[kc + j]), 0.f);
                uint4 hv;
                hv.x = packh2(f[0], f[1]);
                hv.y = packh2(f[2], f[3]);
                hv.z = packh2(f[4], f[5]);
                hv.w = packh2(f[6], f[7]);
                *(uint4*)(smem + G2_A + m * 272 + g * 16) = hv;
            }
            __syncthreads();

            uint32_t bB = sb + G2_B + p * TILEB + boff;
            #pragma unroll
            for (int ks = 0; ks < 8; ks++) {
                uint32_t kb = ks << 5;
                uint32_t aF[4][4];
                #pragma unroll
                for (int mb = 0; mb < 4; mb++) ldsm_x4(aF[mb], aB + mb * 4352 + kb);
                #pragma unroll
                for (int nbp = 0; nbp < 2; nbp++) {
                    uint32_t bh[4];
                    ldsm_x4(bh, bB + nbp * 4352 + kb);
                    #pragma unroll
                    for (int mb = 0; mb < 4; mb++) {
                        mma16816(acc[mb][2*nbp],     aF[mb], bh);
                        mma16816(acc[mb][2*nbp + 1], aF[mb], bh + 2);
                    }
                }
            }
        }

        // epilogue in two 64-row halves staged through the A region
        float* Cs = (float*)(smem + G2_A);   // 64 x 132 floats = 33792 B
        #pragma unroll
        for (int hh = 0; hh < 2; hh++) {
            __syncthreads();
            if ((w & 1) == hh) {
                int mloc = lane >> 2, nc = n0 + 2 * (lane & 3);
                #pragma unroll
                for (int mb = 0; mb < 4; mb++) {
                    #pragma unroll
                    for (int nbq = 0; nbq < 4; nbq++) {
                        int n = nc + nbq * 8;
                        int rr = mloc + mb * 16;
                        *(float2*)(Cs + rr * 132 + n)       = make_float2(acc[mb][nbq][0], acc[mb][nbq][1]);
                        *(float2*)(Cs + (rr + 8) * 132 + n) = make_float2(acc[mb][nbq][2], acc[mb][nbq][3]);
                    }
                }
            }
            __syncthreads();
            if (tid < 64) {
                int grow = row0 + hh * 64 + tid;
                const float* cr = Cs + tid * 132;
                float sum = 0.f, sq = 0.f;
                #pragma unroll
                for (int c = 0; c < 128; c += 4) {
                    float4 q = *(const float4*)(cr + c);
                    float v0 = q.x + s_b2[c], v1 = q.y + s_b2[c+1];
                    float v2 = q.z + s_b2[c+2], v3 = q.w + s_b2[c+3];
                    sum += v0 + v1 + v2 + v3;
                    sq  += v0*v0 + v1*v1 + v2*v2 + v3*v3;
                }
                float mu = sum * (1.f / D);
                float var = sq * (1.f / D) - mu * mu;
                float rr = rsqrtf(var + LN_EPS);
                if (grow < M) {
                    const float4* xr = (const float4*)(x + (size_t)grow * D);
                    float4* po = (float4*)(out + (size_t)grow * D);
                    #pragma unroll
                    for (int c = 0; c < 128; c += 4) {
                        float4 q = *(const float4*)(cr + c);
                        float4 xv = __ldg(xr + (c >> 2));
                        float4 o;
                        o.x = xv.x + fmaxf((q.x + s_b2[c]   - mu) * rr * s_lg[c]   + s_lb[c],   0.f);
                        o.y = xv.y + fmaxf((q.y + s_b2[c+1] - mu) * rr * s_lg[c+1] + s_lb[c+1], 0.f);
                        o.z = xv.z + fmaxf((q.z + s_b2[c+2] - mu) * rr * s_lg[c+2] + s_lb[c+2], 0.f);
                        o.w = xv.w + fmaxf((q.w + s_b2[c+3] - mu) * rr * s_lg[c+3] + s_lb[c+3], 0.f);
                        po[c >> 2] = o;
                    }
                }
            }
        }
    }
}

// ---------------- launcher ---------------------------------------------------
extern "C" void kernel_launch(void* const* d_in, const int* in_sizes, int n_in,
                              void* d_out, int out_size) {
    const float* x        = (const float*)d_in[0];
    const int*   ei       = (const int*)  d_in[1];
    const float* t_ptr    = (const float*)d_in[2];
    const float* W1       = (const float*)d_in[3];
    const float* b1       = (const float*)d_in[4];
    const float* bn_gamma = (const float*)d_in[5];
    const float* bn_beta  = (const float*)d_in[6];
    const float* W2       = (const float*)d_in[7];
    const float* b2       = (const float*)d_in[8];
    const float* ln_gamma = (const float*)d_in[9];
    const float* ln_beta  = (const float*)d_in[10];
    float* out = (float*)d_out;

    int n = in_sizes[0] / D;
    int e = in_sizes[1] / 2;
    const int* src = ei;
    const int* dst = ei + e;
    int nb = (n + 127) / 128;
    int npart = (n + 1023) / 1024;
    int gp1 = nb < 152 ? nb : 152;
    int gp2 = nb < 304 ? nb : 304;
    int work1 = n * 32;
    if (work1 < e) work1 = e;
    if (work1 < 65536) work1 = 65536;
    int hb = (work1 + 1023) / 1024;

    cudaFuncSetAttribute(gemm1_mma, cudaFuncAttributeMaxDynamicSharedMemorySize, G1_SMEM);
    cudaFuncSetAttribute(gemm2_mma, cudaFuncAttributeMaxDynamicSharedMemorySize, G2_SMEM);

    k1_init_hist<<<hb, 1024>>>(W1, W2, x, t_ptr, dst, e, n, npart);
    scan_scatter<<<npart, 1024>>>(src, dst, e, n, npart);
    agg_kernel<<<(n * 32 + 255) / 256, 256>>>(x, n);
    gemm1_mma<<<gp1, 256, G1_SMEM>>>(b1, n, nb);
    bnfinal_kernel<<<1, D2>>>(bn_gamma, bn_beta, n);
    gemm2_mma<<<gp2, 256, G2_SMEM>>>(b2, ln_gamma, ln_beta, x, out, n, nb);
}